// round 6
// baseline (speedup 1.0000x reference)
#include <cuda_runtime.h>
#include <math.h>

#define NB 64
#define NT 512
#define NV 512
#define NH 256
#define NO 512
#define MR (NB * NT)   // 32768 rows

// Scratch (allocation-free rule: __device__ globals)
__device__ float g_xproj[(size_t)MR * NH];   // x@W_ih^T + b_ih + b_hh
__device__ float g_hidden[(size_t)MR * NH];  // min(relu(h),1)

typedef unsigned long long ull;

__device__ __forceinline__ ull fma2(ull a, ull b, ull c) {
    ull d;
    asm("fma.rn.f32x2 %0, %1, %2, %3;" : "=l"(d) : "l"(a), "l"(b), "l"(c));
    return d;
}
__device__ __forceinline__ ull pack2(float lo, float hi) {
    ull r;
    unsigned int l = __float_as_uint(lo), h = __float_as_uint(hi);
    asm("mov.b64 %0, {%1, %2};" : "=l"(r) : "r"(l), "r"(h));
    return r;
}
__device__ __forceinline__ float2 unpack2(ull v) {
    unsigned int l, h;
    asm("mov.b64 {%0, %1}, %2;" : "=r"(l), "=r"(h) : "l"(v));
    return make_float2(__uint_as_float(l), __uint_as_float(h));
}
__device__ __forceinline__ unsigned int s2u(const void* p) {
    return (unsigned int)__cvta_generic_to_shared(p);
}

// ---------------------------------------------------------------------------
// GEMM: C[m,n] = epi( sum_k A[m,k]*Bw[n,k] + bias )   (both operands K-major)
// BM=BN=128, BK=16, 256 threads, 8x8 micro-tile via f32x2 packed FMA.
// Double-buffered smem: one __syncthreads per k-tile.  (unchanged from R4)
// EPI==0: + bias1[n] + bias2[n]      EPI==1: sigmoid(x + bias1[n])
// ---------------------------------------------------------------------------
template<int EPI>
__global__ void __launch_bounds__(256, 2)
gemm_nt(const float* __restrict__ A, const float* __restrict__ Bw,
        const float* __restrict__ bias1, const float* __restrict__ bias2,
        float* __restrict__ C, int M, int N, int K)
{
    __shared__ __align__(16) float As[2][16][132];
    __shared__ __align__(16) float Bs[2][16][132];
    const int tid = threadIdx.x;
    const int m0 = blockIdx.y << 7;
    const int n0 = blockIdx.x << 7;
    const int ar = tid >> 2;          // 0..63
    const int ac = (tid & 3) << 2;    // 0,4,8,12
    const float* Ag = A  + (size_t)(m0 + ar) * K + ac;
    const float* Bg = Bw + (size_t)(n0 + ar) * K + ac;
    const int tm = tid >> 4;          // 0..15 (row group of 8)
    const int tn = tid & 15;          // 0..15 (col group: tn*4 and tn*4+64)

    ull acc[4][8];
#pragma unroll
    for (int i = 0; i < 4; i++)
#pragma unroll
        for (int j = 0; j < 8; j++) acc[i][j] = 0ull;

    float4 a0 = *(const float4*)(Ag);
    float4 a1 = *(const float4*)(Ag + (size_t)64 * K);
    float4 b0 = *(const float4*)(Bg);
    float4 b1 = *(const float4*)(Bg + (size_t)64 * K);
    int buf = 0;
    {
        As[0][ac + 0][ar]      = a0.x; As[0][ac + 1][ar]      = a0.y;
        As[0][ac + 2][ar]      = a0.z; As[0][ac + 3][ar]      = a0.w;
        As[0][ac + 0][ar + 64] = a1.x; As[0][ac + 1][ar + 64] = a1.y;
        As[0][ac + 2][ar + 64] = a1.z; As[0][ac + 3][ar + 64] = a1.w;
        Bs[0][ac + 0][ar]      = b0.x; Bs[0][ac + 1][ar]      = b0.y;
        Bs[0][ac + 2][ar]      = b0.z; Bs[0][ac + 3][ar]      = b0.w;
        Bs[0][ac + 0][ar + 64] = b1.x; Bs[0][ac + 1][ar + 64] = b1.y;
        Bs[0][ac + 2][ar + 64] = b1.z; Bs[0][ac + 3][ar + 64] = b1.w;
    }
    __syncthreads();

    for (int k0 = 0; k0 < K; k0 += 16) {
        const bool more = (k0 + 16) < K;
        if (more) {
            Ag += 16; Bg += 16;
            a0 = *(const float4*)(Ag);
            a1 = *(const float4*)(Ag + (size_t)64 * K);
            b0 = *(const float4*)(Bg);
            b1 = *(const float4*)(Bg + (size_t)64 * K);
        }
#pragma unroll
        for (int k = 0; k < 16; k++) {
            ulonglong2 aA = *(const ulonglong2*)&As[buf][k][tm * 8];
            ulonglong2 aB = *(const ulonglong2*)&As[buf][k][tm * 8 + 4];
            float4 bA = *(const float4*)&Bs[buf][k][tn * 4];
            float4 bB = *(const float4*)&Bs[buf][k][tn * 4 + 64];
            ull a2[4] = { aA.x, aA.y, aB.x, aB.y };
            ull bb[8] = { pack2(bA.x, bA.x), pack2(bA.y, bA.y),
                          pack2(bA.z, bA.z), pack2(bA.w, bA.w),
                          pack2(bB.x, bB.x), pack2(bB.y, bB.y),
                          pack2(bB.z, bB.z), pack2(bB.w, bB.w) };
#pragma unroll
            for (int j = 0; j < 8; j++)
#pragma unroll
                for (int i = 0; i < 4; i++)
                    acc[i][j] = fma2(a2[i], bb[j], acc[i][j]);
        }
        if (more) {
            int nb = buf ^ 1;
            As[nb][ac + 0][ar]      = a0.x; As[nb][ac + 1][ar]      = a0.y;
            As[nb][ac + 2][ar]      = a0.z; As[nb][ac + 3][ar]      = a0.w;
            As[nb][ac + 0][ar + 64] = a1.x; As[nb][ac + 1][ar + 64] = a1.y;
            As[nb][ac + 2][ar + 64] = a1.z; As[nb][ac + 3][ar + 64] = a1.w;
            Bs[nb][ac + 0][ar]      = b0.x; Bs[nb][ac + 1][ar]      = b0.y;
            Bs[nb][ac + 2][ar]      = b0.z; Bs[nb][ac + 3][ar]      = b0.w;
            Bs[nb][ac + 0][ar + 64] = b1.x; Bs[nb][ac + 1][ar + 64] = b1.y;
            Bs[nb][ac + 2][ar + 64] = b1.z; Bs[nb][ac + 3][ar + 64] = b1.w;
            __syncthreads();
            buf = nb;
        }
    }

    float bv[8];
#pragma unroll
    for (int j = 0; j < 4; j++) {
        bv[j]     = bias1[n0 + tn * 4 + j];
        bv[4 + j] = bias1[n0 + tn * 4 + 64 + j];
    }
    if (EPI == 0) {
#pragma unroll
        for (int j = 0; j < 4; j++) {
            bv[j]     += bias2[n0 + tn * 4 + j];
            bv[4 + j] += bias2[n0 + tn * 4 + 64 + j];
        }
    }
#pragma unroll
    for (int i2 = 0; i2 < 4; i2++) {
        float2 v[8];
#pragma unroll
        for (int j = 0; j < 8; j++) v[j] = unpack2(acc[i2][j]);
#pragma unroll
        for (int half = 0; half < 2; half++) {
            int m = m0 + tm * 8 + i2 * 2 + half;
            float r[8];
#pragma unroll
            for (int j = 0; j < 8; j++) {
                float x = (half ? v[j].y : v[j].x) + bv[j];
                if (EPI == 1) x = 1.0f / (1.0f + expf(-x));
                r[j] = x;
            }
            *(float4*)&C[(size_t)m * N + n0 + tn * 4]      = make_float4(r[0], r[1], r[2], r[3]);
            *(float4*)&C[(size_t)m * N + n0 + tn * 4 + 64] = make_float4(r[4], r[5], r[6], r[7]);
        }
    }
}

// ---------------------------------------------------------------------------
// Recurrence: 64 clusters of 2 CTAs, one batch per cluster.
// CTA rank r computes h[cols r*128 .. +128). Each col's 256-j dot is split
// between adjacent lanes: part=tid&1 (0: local-j half, 1: peer-j half),
// combined by shfl_xor(1). Per-step cross-CTA traffic: 128 weak DSMEM stores
// (h values) + ONE fence.acq_rel.cluster + ONE remote flag store (tid0).
// Consumers spin on a local smem monotonic step counter with ld.acquire.
// Double-buffered h_loc/rbuf (slot = t&1) make the protocol hazard-free.
// ---------------------------------------------------------------------------
__global__ void __cluster_dims__(2, 1, 1) __launch_bounds__(256, 1)
rnn_scan(const float* __restrict__ W_hh, const float* __restrict__ prev,
         float* __restrict__ hn_out)
{
    __shared__ __align__(16) float h_loc[2][128];  // this CTA's own half of v_t
    __shared__ __align__(16) float rbuf[2][128];   // peer's half of v_t
    __shared__ unsigned int flag;                  // steps of peer data landed
    const int tid = threadIdx.x;
    const int b = blockIdx.x >> 1;
    unsigned int rank;
    asm("mov.u32 %0, %%cluster_ctarank;" : "=r"(rank));
    const unsigned int peer = rank ^ 1u;
    const int part  = tid & 1;          // 0: local-j partial, 1: remote-j partial
    const int col_l = tid >> 1;         // local output col 0..127
    const int col   = (int)rank * 128 + col_l;

    // This thread's 128 weights: W_hh[col][jbase .. jbase+127] as 64 f32x2
    ull w2[64];
    {
        const int jbase = (part ? (int)peer : (int)rank) * 128;
        const ull* wrow = (const ull*)(W_hh + (size_t)col * NH + jbase);
#pragma unroll
        for (int q = 0; q < 64; q++) w2[q] = wrow[q];
    }

    // Init v_0 = prev: both halves available without comms
    if (tid < 128) {
        h_loc[0][tid] = prev[b * NH + (int)rank * 128 + tid];
        rbuf[0][tid]  = prev[b * NH + (int)peer * 128 + tid];
    }
    if (tid == 0) flag = 0;
    __syncthreads();
    asm volatile("barrier.cluster.arrive.aligned;" ::: "memory");
    asm volatile("barrier.cluster.wait.aligned;"   ::: "memory");

    // Remote addresses: peer's rbuf slots (for our h) + peer's flag
    unsigned int rem_h[2], rem_flag;
    {
        unsigned int l0 = s2u(&rbuf[0][col_l]);
        unsigned int l1 = s2u(&rbuf[1][col_l]);
        unsigned int lf = s2u(&flag);
        asm("mapa.shared::cluster.u32 %0, %1, %2;" : "=r"(rem_h[0]) : "r"(l0), "r"(peer));
        asm("mapa.shared::cluster.u32 %0, %1, %2;" : "=r"(rem_h[1]) : "r"(l1), "r"(peer));
        asm("mapa.shared::cluster.u32 %0, %1, %2;" : "=r"(rem_flag) : "r"(lf), "r"(peer));
    }
    const unsigned int loc_flag = s2u(&flag);
    const ulonglong2* src[2];
    src[0] = part ? (const ulonglong2*)&rbuf[0][0] : (const ulonglong2*)&h_loc[0][0];
    src[1] = part ? (const ulonglong2*)&rbuf[1][0] : (const ulonglong2*)&h_loc[1][0];

    const float* xrow  = g_xproj  + ((size_t)b * NT) * NH + col;
    float*       hidro = g_hidden + ((size_t)b * NT) * NH + col;
    // xp prefetch pipeline depth 2 (even lanes only; odd lanes get it via shfl)
    float xp0 = part ? 0.0f : xrow[0];
    float xp1 = part ? 0.0f : xrow[NH];

    for (int t = 0; t < NT; t++) {
        float xp = xp0;
        xp0 = xp1;
        if (!part && t + 2 < NT) xp1 = xrow[(size_t)(t + 2) * NH];

        if (part) {  // wait for peer half of v_t (no wait at t=0)
            unsigned int f;
            do {
                asm volatile("ld.acquire.cluster.shared::cta.u32 %0, [%1];"
                             : "=r"(f) : "r"(loc_flag) : "memory");
            } while (f < (unsigned int)t);
        }

        const ulonglong2* h4 = src[t & 1];
        ull a0 = 0ull, a1 = 0ull, a2 = 0ull, a3 = 0ull;   // 4 chains, depth 16
#pragma unroll
        for (int q = 0; q < 16; q++) {
            ulonglong2 u = h4[2 * q];
            ulonglong2 v = h4[2 * q + 1];
            a0 = fma2(w2[4 * q],     u.x, a0);
            a1 = fma2(w2[4 * q + 1], u.y, a1);
            a2 = fma2(w2[4 * q + 2], v.x, a2);
            a3 = fma2(w2[4 * q + 3], v.y, a3);
        }
        float2 f0 = unpack2(a0), f1 = unpack2(a1), f2 = unpack2(a2), f3 = unpack2(a3);
        float acc = ((f0.x + f0.y) + (f1.x + f1.y)) + ((f2.x + f2.y) + (f3.x + f3.y));
        float tot = acc + __shfl_xor_sync(0xffffffffu, acc, 1);
        float xps = __shfl_xor_sync(0xffffffffu, xp, 1);

        float h = fmaxf(tot + (part ? xps : xp), 0.0f);
        const int nb = (t + 1) & 1;
        if (part == 0) {
            h_loc[nb][col_l] = h;                       // own half for next step
            unsigned int hb = __float_as_uint(h);
            unsigned int ra = nb ? rem_h[1] : rem_h[0]; // peer copy (weak store)
            asm volatile("st.shared::cluster.b32 [%0], %1;" :: "r"(ra), "r"(hb) : "memory");
        } else {
            hidro[(size_t)t * NH] = fminf(h, 1.0f);     // capped lrelu (h>=0)
            if (t == NT - 1) hn_out[b * NH + col] = h;
        }
        __syncthreads();  // h_loc[nb] complete; all remote stores issued
        if (tid == 0) {   // one release fence + one remote flag store per step
            asm volatile("fence.acq_rel.cluster;" ::: "memory");
            asm volatile("st.relaxed.cluster.shared::cluster.u32 [%0], %1;"
                         :: "r"(rem_flag), "r"((unsigned int)(t + 1)) : "memory");
        }
    }
    asm volatile("barrier.cluster.arrive.aligned;" ::: "memory");
    asm volatile("barrier.cluster.wait.aligned;"   ::: "memory");
}

// ---------------------------------------------------------------------------
extern "C" void kernel_launch(void* const* d_in, const int* in_sizes, int n_in,
                              void* d_out, int out_size)
{
    const float* sentence = (const float*)d_in[0];
    const float* prev     = (const float*)d_in[1];
    const float* W_ih     = (const float*)d_in[2];
    const float* b_ih     = (const float*)d_in[3];
    const float* W_hh     = (const float*)d_in[4];
    const float* b_hh     = (const float*)d_in[5];
    const float* W_out    = (const float*)d_in[6];
    const float* b_out    = (const float*)d_in[7];
    float* out = (float*)d_out;

    float* xproj = nullptr;
    float* hidden = nullptr;
    cudaGetSymbolAddress((void**)&xproj, g_xproj);
    cudaGetSymbolAddress((void**)&hidden, g_hidden);

    // Phase 1: x_proj = sentence @ W_ih^T + (b_ih + b_hh)
    gemm_nt<0><<<dim3(NH / 128, MR / 128), 256>>>(sentence, W_ih, b_ih, b_hh,
                                                  xproj, MR, NH, NV);
    // Phase 2: sequential scan; writes g_hidden and h_n (tail of d_out)
    rnn_scan<<<NB * 2, 256>>>(W_hh, prev, out + (size_t)MR * NO);
    // Phase 3: tags = sigmoid(hidden @ W_out^T + b_out)
    gemm_nt<1><<<dim3(NO / 128, MR / 128), 256>>>(hidden, W_out, b_out, nullptr,
                                                  out, MR, NO, NH);
}

// round 10
// speedup vs baseline: 1.7121x; 1.7121x over previous
#include <cuda_runtime.h>
#include <math.h>

#define NB 64
#define NT 512
#define NV 512
#define NH 256
#define NO 512
#define MR (NB * NT)   // 32768 rows

// Scratch (allocation-free rule: __device__ globals)
__device__ float g_xproj[(size_t)MR * NH];   // x@W_ih^T + b_ih + b_hh
__device__ float g_hidden[(size_t)MR * NH];  // min(relu(h),1)

typedef unsigned long long ull;

__device__ __forceinline__ ull fma2(ull a, ull b, ull c) {
    ull d;
    asm("fma.rn.f32x2 %0, %1, %2, %3;" : "=l"(d) : "l"(a), "l"(b), "l"(c));
    return d;
}
__device__ __forceinline__ ull pack2(float lo, float hi) {
    ull r;
    unsigned int l = __float_as_uint(lo), h = __float_as_uint(hi);
    asm("mov.b64 %0, {%1, %2};" : "=l"(r) : "r"(l), "r"(h));
    return r;
}
__device__ __forceinline__ float2 unpack2(ull v) {
    unsigned int l, h;
    asm("mov.b64 {%0, %1}, %2;" : "=r"(l), "=r"(h) : "l"(v));
    return make_float2(__uint_as_float(l), __uint_as_float(h));
}

// ---------------------------------------------------------------------------
// GEMM: C[m,n] = epi( sum_k A[m,k]*Bw[n,k] + bias )   (both operands K-major)
// BM=BN=128, BK=16, 256 threads, 8x8 micro-tile via f32x2 packed FMA.
// Double-buffered smem: one __syncthreads per k-tile.  (measured 173us)
// EPI==0: + bias1[n] + bias2[n]      EPI==1: sigmoid(x + bias1[n])
// ---------------------------------------------------------------------------
template<int EPI>
__global__ void __launch_bounds__(256, 2)
gemm_nt(const float* __restrict__ A, const float* __restrict__ Bw,
        const float* __restrict__ bias1, const float* __restrict__ bias2,
        float* __restrict__ C, int M, int N, int K)
{
    __shared__ __align__(16) float As[2][16][132];
    __shared__ __align__(16) float Bs[2][16][132];
    const int tid = threadIdx.x;
    const int m0 = blockIdx.y << 7;
    const int n0 = blockIdx.x << 7;
    const int ar = tid >> 2;          // 0..63
    const int ac = (tid & 3) << 2;    // 0,4,8,12
    const float* Ag = A  + (size_t)(m0 + ar) * K + ac;
    const float* Bg = Bw + (size_t)(n0 + ar) * K + ac;
    const int tm = tid >> 4;          // 0..15 (row group of 8)
    const int tn = tid & 15;          // 0..15 (col group: tn*4 and tn*4+64)

    ull acc[4][8];
#pragma unroll
    for (int i = 0; i < 4; i++)
#pragma unroll
        for (int j = 0; j < 8; j++) acc[i][j] = 0ull;

    float4 a0 = *(const float4*)(Ag);
    float4 a1 = *(const float4*)(Ag + (size_t)64 * K);
    float4 b0 = *(const float4*)(Bg);
    float4 b1 = *(const float4*)(Bg + (size_t)64 * K);
    int buf = 0;
    {
        As[0][ac + 0][ar]      = a0.x; As[0][ac + 1][ar]      = a0.y;
        As[0][ac + 2][ar]      = a0.z; As[0][ac + 3][ar]      = a0.w;
        As[0][ac + 0][ar + 64] = a1.x; As[0][ac + 1][ar + 64] = a1.y;
        As[0][ac + 2][ar + 64] = a1.z; As[0][ac + 3][ar + 64] = a1.w;
        Bs[0][ac + 0][ar]      = b0.x; Bs[0][ac + 1][ar]      = b0.y;
        Bs[0][ac + 2][ar]      = b0.z; Bs[0][ac + 3][ar]      = b0.w;
        Bs[0][ac + 0][ar + 64] = b1.x; Bs[0][ac + 1][ar + 64] = b1.y;
        Bs[0][ac + 2][ar + 64] = b1.z; Bs[0][ac + 3][ar + 64] = b1.w;
    }
    __syncthreads();

    for (int k0 = 0; k0 < K; k0 += 16) {
        const bool more = (k0 + 16) < K;
        if (more) {
            Ag += 16; Bg += 16;
            a0 = *(const float4*)(Ag);
            a1 = *(const float4*)(Ag + (size_t)64 * K);
            b0 = *(const float4*)(Bg);
            b1 = *(const float4*)(Bg + (size_t)64 * K);
        }
#pragma unroll
        for (int k = 0; k < 16; k++) {
            ulonglong2 aA = *(const ulonglong2*)&As[buf][k][tm * 8];
            ulonglong2 aB = *(const ulonglong2*)&As[buf][k][tm * 8 + 4];
            float4 bA = *(const float4*)&Bs[buf][k][tn * 4];
            float4 bB = *(const float4*)&Bs[buf][k][tn * 4 + 64];
            ull a2[4] = { aA.x, aA.y, aB.x, aB.y };
            ull bb[8] = { pack2(bA.x, bA.x), pack2(bA.y, bA.y),
                          pack2(bA.z, bA.z), pack2(bA.w, bA.w),
                          pack2(bB.x, bB.x), pack2(bB.y, bB.y),
                          pack2(bB.z, bB.z), pack2(bB.w, bB.w) };
#pragma unroll
            for (int j = 0; j < 8; j++)
#pragma unroll
                for (int i = 0; i < 4; i++)
                    acc[i][j] = fma2(a2[i], bb[j], acc[i][j]);
        }
        if (more) {
            int nb = buf ^ 1;
            As[nb][ac + 0][ar]      = a0.x; As[nb][ac + 1][ar]      = a0.y;
            As[nb][ac + 2][ar]      = a0.z; As[nb][ac + 3][ar]      = a0.w;
            As[nb][ac + 0][ar + 64] = a1.x; As[nb][ac + 1][ar + 64] = a1.y;
            As[nb][ac + 2][ar + 64] = a1.z; As[nb][ac + 3][ar + 64] = a1.w;
            Bs[nb][ac + 0][ar]      = b0.x; Bs[nb][ac + 1][ar]      = b0.y;
            Bs[nb][ac + 2][ar]      = b0.z; Bs[nb][ac + 3][ar]      = b0.w;
            Bs[nb][ac + 0][ar + 64] = b1.x; Bs[nb][ac + 1][ar + 64] = b1.y;
            Bs[nb][ac + 2][ar + 64] = b1.z; Bs[nb][ac + 3][ar + 64] = b1.w;
            __syncthreads();
            buf = nb;
        }
    }

    float bv[8];
#pragma unroll
    for (int j = 0; j < 4; j++) {
        bv[j]     = bias1[n0 + tn * 4 + j];
        bv[4 + j] = bias1[n0 + tn * 4 + 64 + j];
    }
    if (EPI == 0) {
#pragma unroll
        for (int j = 0; j < 4; j++) {
            bv[j]     += bias2[n0 + tn * 4 + j];
            bv[4 + j] += bias2[n0 + tn * 4 + 64 + j];
        }
    }
#pragma unroll
    for (int i2 = 0; i2 < 4; i2++) {
        float2 v[8];
#pragma unroll
        for (int j = 0; j < 8; j++) v[j] = unpack2(acc[i2][j]);
#pragma unroll
        for (int half = 0; half < 2; half++) {
            int m = m0 + tm * 8 + i2 * 2 + half;
            float r[8];
#pragma unroll
            for (int j = 0; j < 8; j++) {
                float x = (half ? v[j].y : v[j].x) + bv[j];
                if (EPI == 1) x = 1.0f / (1.0f + expf(-x));
                r[j] = x;
            }
            *(float4*)&C[(size_t)m * N + n0 + tn * 4]      = make_float4(r[0], r[1], r[2], r[3]);
            *(float4*)&C[(size_t)m * N + n0 + tn * 4 + 64] = make_float4(r[4], r[5], r[6], r[7]);
        }
    }
}

// ---------------------------------------------------------------------------
// Recurrence: ONE CTA (256 threads) per batch element. No clusters, no DSMEM.
// Thread t owns output column col=t: full 256-j dot product per step.
//   W_hh[col][  0:192) -> 96 ull registers (192 regs/thread)
//   W_hh[col][192:256) -> dynamic smem ws2[i][col] (64 KB, conflict-free:
//                         lane l reads ws2[i][col=l+base], 8B stride)
// h: double-buffered smem float[2][256]; loads are warp-broadcast (free).
// Per step: 128 fma2 + 1 __syncthreads. Issue wall ~512 cyc/step.
// ---------------------------------------------------------------------------
#define WS_ULL 32   // 32 ull = 64 floats per column from smem (js 192..255)

__global__ void __launch_bounds__(256, 1)
rnn_scan(const float* __restrict__ W_hh, const float* __restrict__ prev,
         float* __restrict__ hn_out)
{
    extern __shared__ __align__(16) char smem_raw[];
    ull*   ws2 = (ull*)smem_raw;                       // [WS_ULL][256] -> 64 KB
    float* hb  = (float*)(smem_raw + WS_ULL * 256 * sizeof(ull)); // [2][256]

    const int col = threadIdx.x;      // 0..255, one output column per thread
    const int b   = blockIdx.x;

    // Register weights: W_hh[col][0:192) as 96 f32x2
    ull w2[96];
    {
        const ull* wrow = (const ull*)(W_hh + (size_t)col * NH);
#pragma unroll
        for (int q = 0; q < 96; q++) w2[q] = wrow[q];
        // Smem weights: W_hh[col][192:256) -> ws2[i][col]
#pragma unroll
        for (int i = 0; i < WS_ULL; i++) ws2[i * 256 + col] = wrow[96 + i];
    }

    // h0
    hb[col] = prev[b * NH + col];
    __syncthreads();

    const float* xrow  = g_xproj  + ((size_t)b * NT) * NH + col;
    float*       hidro = g_hidden + ((size_t)b * NT) * NH + col;
    float xp0 = xrow[0];
    float xp1 = xrow[NH];

    int p = 0;
    for (int t = 0; t < NT; t++) {
        float xp = xp0;
        xp0 = xp1;
        if (t + 2 < NT) xp1 = xrow[(size_t)(t + 2) * NH];   // depth-2 prefetch

        const ulonglong2* hp = (const ulonglong2*)(hb + p * 256);
        ull a0 = 0ull, a1 = 0ull, a2 = 0ull, a3 = 0ull;     // 4 chains
        // register-weight part: js 0..191 (48 x 16B h chunks, broadcast)
#pragma unroll
        for (int q = 0; q < 24; q++) {
            ulonglong2 h0 = hp[2 * q];
            ulonglong2 h1 = hp[2 * q + 1];
            a0 = fma2(w2[4 * q],     h0.x, a0);
            a1 = fma2(w2[4 * q + 1], h0.y, a1);
            a2 = fma2(w2[4 * q + 2], h1.x, a2);
            a3 = fma2(w2[4 * q + 3], h1.y, a3);
        }
        // smem-weight part: js 192..255 (16 x 16B h chunks)
#pragma unroll
        for (int q = 0; q < 16; q++) {
            ulonglong2 hv = hp[48 + q];
            ull wA = ws2[(2 * q)     * 256 + col];
            ull wB = ws2[(2 * q + 1) * 256 + col];
            a0 = fma2(wA, hv.x, a0);
            a1 = fma2(wB, hv.y, a1);
        }
        float2 f0 = unpack2(a0), f1 = unpack2(a1), f2 = unpack2(a2), f3 = unpack2(a3);
        float tot = ((f0.x + f0.y) + (f1.x + f1.y)) + ((f2.x + f2.y) + (f3.x + f3.y));

        float h = fmaxf(tot + xp, 0.0f);
        hb[(p ^ 1) * 256 + col] = h;                 // next step's h
        // streaming store: g_hidden is consumed by a later kernel; don't
        // displace L2 working set with 32 MB of write-once data
        asm volatile("st.global.cs.f32 [%0], %1;"
                     :: "l"(hidro + (size_t)t * NH), "f"(fminf(h, 1.0f)) : "memory");
        if (t == NT - 1) hn_out[b * NH + col] = h;
        __syncthreads();
        p ^= 1;
    }
}

// ---------------------------------------------------------------------------
extern "C" void kernel_launch(void* const* d_in, const int* in_sizes, int n_in,
                              void* d_out, int out_size)
{
    const float* sentence = (const float*)d_in[0];
    const float* prev     = (const float*)d_in[1];
    const float* W_ih     = (const float*)d_in[2];
    const float* b_ih     = (const float*)d_in[3];
    const float* W_hh     = (const float*)d_in[4];
    const float* b_hh     = (const float*)d_in[5];
    const float* W_out    = (const float*)d_in[6];
    const float* b_out    = (const float*)d_in[7];
    float* out = (float*)d_out;

    float* xproj = nullptr;
    float* hidden = nullptr;
    cudaGetSymbolAddress((void**)&xproj, g_xproj);
    cudaGetSymbolAddress((void**)&hidden, g_hidden);

    const int scan_smem = WS_ULL * 256 * (int)sizeof(ull) + 2 * 256 * (int)sizeof(float);
    cudaFuncSetAttribute(rnn_scan, cudaFuncAttributeMaxDynamicSharedMemorySize,
                         scan_smem);  // idempotent, non-enqueuing: capture-safe

    // Phase 1: x_proj = sentence @ W_ih^T + (b_ih + b_hh)
    gemm_nt<0><<<dim3(NH / 128, MR / 128), 256>>>(sentence, W_ih, b_ih, b_hh,
                                                  xproj, MR, NH, NV);
    // Phase 2: sequential scan; writes g_hidden and h_n (tail of d_out)
    rnn_scan<<<NB, 256, scan_smem>>>(W_hh, prev, out + (size_t)MR * NO);
    // Phase 3: tags = sigmoid(hidden @ W_out^T + b_out)
    gemm_nt<1><<<dim3(NO / 128, MR / 128), 256>>>(hidden, W_out, b_out, nullptr,
                                                  out, MR, NO, NH);
}